// round 7
// baseline (speedup 1.0000x reference)
#include <cuda_runtime.h>
#include <cuda_fp16.h>
#include <math.h>
#include <stdint.h>

#define HDIM 1024
#define NDIM 2048
#define NEXP 8
#define MTOK 16384
#define BM 128
#define BN 128
#define BK 32
#define KT (HDIM / BK)
#define GAP_TH 2e-4f
#define MAXFLAG 4096

#define ST_AH 0
#define ST_A8 10240
#define ST_BH 20480
#define ST_B8 30720
#define STG   40960
#define OFF_W2 (2 * STG)
#define OFF_B1 (OFF_W2 + BN * NEXP * 4)
#define SMEM_DYN (OFF_B1 + BN * 4)

__device__ __half g_wh[NDIM * HDIM];
__device__ __half g_wl[NDIM * HDIM];
__device__ uint2  g_w8[NDIM * (HDIM / 4)];   // (bh8,bl8) packed 4k per word
__device__ float  g_usage[NEXP];
__device__ int    g_count, g_nflag, g_done;
__device__ int    g_list[MAXFLAG];

__device__ __forceinline__ uint32_t smem_u32(const void* p) {
    uint32_t a;
    asm("{ .reg .u64 t; cvta.to.shared.u64 t, %1; cvt.u32.u64 %0, t; }" : "=r"(a) : "l"(p));
    return a;
}
__device__ __forceinline__ void cp16(uint32_t s, const void* g) {
    asm volatile("cp.async.cg.shared.global [%0], [%1], 16;" :: "r"(s), "l"(g));
}
__device__ __forceinline__ void cp_commit() { asm volatile("cp.async.commit_group;" ::: "memory"); }
__device__ __forceinline__ void cp_wait0()  { asm volatile("cp.async.wait_group 0;" ::: "memory"); }
__device__ __forceinline__ void ldm4(uint32_t* r, uint32_t a) {
    asm volatile("ldmatrix.sync.aligned.m8n8.x4.shared.b16 {%0,%1,%2,%3}, [%4];"
                 : "=r"(r[0]), "=r"(r[1]), "=r"(r[2]), "=r"(r[3]) : "r"(a));
}
__device__ __forceinline__ void mma_f16(float* c, const uint32_t* a, const uint32_t* b) {
    asm volatile("mma.sync.aligned.m16n8k16.row.col.f32.f16.f16.f32 "
                 "{%0,%1,%2,%3}, {%4,%5,%6,%7}, {%8,%9}, {%0,%1,%2,%3};"
                 : "+f"(c[0]), "+f"(c[1]), "+f"(c[2]), "+f"(c[3])
                 : "r"(a[0]), "r"(a[1]), "r"(a[2]), "r"(a[3]), "r"(b[0]), "r"(b[1]));
}
__device__ __forceinline__ void mma_s8(int* c, uint32_t a0, uint32_t a1, uint32_t a2,
                                       uint32_t a3, uint32_t b0, uint32_t b1) {
    asm volatile("mma.sync.aligned.m16n8k32.row.col.s32.s8.s8.s32 "
                 "{%0,%1,%2,%3}, {%4,%5,%6,%7}, {%8,%9}, {%0,%1,%2,%3};"
                 : "+r"(c[0]), "+r"(c[1]), "+r"(c[2]), "+r"(c[3])
                 : "r"(a0), "r"(a1), "r"(a2), "r"(a3), "r"(b0), "r"(b1));
}
__device__ __forceinline__ uint2 lds64(uint32_t a) {
    uint2 r;
    asm volatile("ld.shared.v2.u32 {%0,%1}, [%2];" : "=r"(r.x), "=r"(r.y) : "r"(a));
    return r;
}

// ---------- kernel 0: w1^T split (fp16 hi/lo + int8 pack) + init ----------
__global__ void pre_kernel(const float* __restrict__ w1, float* __restrict__ ew,
                           const float* __restrict__ b2) {
    __shared__ float tile[32][33];
    const int b = blockIdx.x, t = threadIdx.x;
    if (b < 2048) {
        const int nb = (b & 63) * 32, kb = (b >> 6) * 32;
        const int tx = t & 31, ty = t >> 5;
#pragma unroll
        for (int i = 0; i < 4; ++i)
            tile[ty + i * 8][tx] = w1[(size_t)(kb + ty + i * 8) * NDIM + nb + tx];
        __syncthreads();
        const int r = t >> 3, kw = t & 7;       // n-row, k-word
        __half h[4], l[4];
        uint32_t bwh = 0, bwl = 0;
#pragma unroll
        for (int j = 0; j < 4; ++j) {
            float v = tile[kw * 4 + j][r] * 1024.0f;
            h[j] = __float2half_rn(v);
            float hf = __half2float(h[j]);
            l[j] = __float2half_rn(v - hf);
            int hi8 = __float2int_rn(fminf(fmaxf(hf, -127.f), 127.f)) & 255;
            int lo8 = __float2int_rn(fminf(fmaxf((v - hf) * 2048.f, -127.f), 127.f)) & 255;
            bwh |= (uint32_t)hi8 << (j * 8);
            bwl |= (uint32_t)lo8 << (j * 8);
        }
        size_t ho = (size_t)(nb + r) * HDIM + kw * 4 + kb;
        __half2 h01 = __halves2half2(h[0], h[1]), h23 = __halves2half2(h[2], h[3]);
        __half2 l01 = __halves2half2(l[0], l[1]), l23 = __halves2half2(l[2], l[3]);
        *(uint2*)(g_wh + ho) = make_uint2(*(uint32_t*)&h01, *(uint32_t*)&h23);
        *(uint2*)(g_wl + ho) = make_uint2(*(uint32_t*)&l01, *(uint32_t*)&l23);
        g_w8[(size_t)(nb + r) * (HDIM / 4) + (kb >> 2) + kw] = make_uint2(bwh, bwl);
    } else {
        const int i = (b - 2048) * 256 + t;
        if (i < MTOK * NEXP) ew[i] = b2[i & 7];
        if (b == 2048) {
            if (t < NEXP) g_usage[t] = 0.f;
            if (t == 0) { g_count = 0; g_nflag = 0; g_done = 0; }
        }
    }
}

// ---------- kernel 1: GEMM (fp16 hi.hi + int8 crosses) + GELU + GEMM2 ----------
__global__ __launch_bounds__(256, 2)
void gemm_kernel(const float* __restrict__ x, const float* __restrict__ b1,
                 const float* __restrict__ w2, float* __restrict__ ew) {
    extern __shared__ char smem[];
    const uint32_t sb = smem_u32(smem);
    const int t = threadIdx.x, w = t >> 5, lane = t & 31;
    const int wm = w & 3, wn = w >> 2;
    const int n0 = blockIdx.x * BN, m0 = blockIdx.y * BM;

    float* w2s = (float*)(smem + OFF_W2);
    float* b1s = (float*)(smem + OFF_B1);
    for (int i = t; i < BN * NEXP; i += 256) w2s[i] = w2[(size_t)n0 * NEXP + i];
    for (int i = t; i < BN; i += 256)        b1s[i] = b1[n0 + i];

    const int rA = t >> 1;
    const float* xg = x + (size_t)(m0 + rA) * HDIM + (t & 1) * 16;
    const size_t gbh = (size_t)(n0 + rA) * HDIM;
    const char* g8row = (const char*)(g_w8 + (size_t)(n0 + rA) * (HDIM / 4));

#define LOAD_B(stg, kt_)                                                     \
    {                                                                        \
        uint32_t _bs = sb + (stg) * STG + rA * 80;                           \
        size_t _kb = gbh + (size_t)(kt_) * BK;                               \
        const char* _g8 = g8row + (size_t)(kt_) * 64;                        \
        _Pragma("unroll")                                                    \
        for (int j = 0; j < 2; ++j) {                                        \
            int c16 = (t & 1) * 2 + j;                                       \
            cp16(_bs + ST_BH + c16 * 16, g_wh + _kb + c16 * 8);              \
            cp16(_bs + ST_B8 + c16 * 16, _g8 + c16 * 16);                    \
        }                                                                    \
    }

#define STS_A(stg, ra_)                                                      \
    {                                                                        \
        uint32_t hws[8], a8[8];                                              \
        _Pragma("unroll")                                                    \
        for (int wi = 0; wi < 4; ++wi) {                                     \
            const float* fp = (const float*)&(ra_)[wi];                      \
            __half h0 = __float2half_rn(fp[0]), h1 = __float2half_rn(fp[1]); \
            __half h2 = __float2half_rn(fp[2]), h3 = __float2half_rn(fp[3]); \
            float g0 = __half2float(h0), g1 = __half2float(h1);              \
            float g2 = __half2float(h2), g3 = __half2float(h3);              \
            __half2 p01 = __halves2half2(h0, h1), p23 = __halves2half2(h2, h3);\
            hws[wi*2] = *(uint32_t*)&p01; hws[wi*2+1] = *(uint32_t*)&p23;    \
            a8[wi*2] = (uint32_t)(__float2int_rn(g0*16.f) & 255)             \
                | ((uint32_t)(__float2int_rn(g1*16.f) & 255) << 8)           \
                | ((uint32_t)(__float2int_rn(g2*16.f) & 255) << 16)          \
                | ((uint32_t)(__float2int_rn(g3*16.f) & 255) << 24);         \
            a8[wi*2+1] = (uint32_t)(__float2int_rn((fp[0]-g0)*32768.f) & 255)\
                | ((uint32_t)(__float2int_rn((fp[1]-g1)*32768.f) & 255) << 8)\
                | ((uint32_t)(__float2int_rn((fp[2]-g2)*32768.f) & 255) << 16)\
                | ((uint32_t)(__float2int_rn((fp[3]-g3)*32768.f) & 255) << 24);\
        }                                                                    \
        char* _p = smem + (stg) * STG + rA * 80 + (t & 1) * 32;              \
        *(uint4*)(_p + ST_AH)      = make_uint4(hws[0], hws[1], hws[2], hws[3]);\
        *(uint4*)(_p + ST_AH + 16) = make_uint4(hws[4], hws[5], hws[6], hws[7]);\
        *(uint4*)(_p + ST_A8)      = make_uint4(a8[0], a8[1], a8[2], a8[3]); \
        *(uint4*)(_p + ST_A8 + 16) = make_uint4(a8[4], a8[5], a8[6], a8[7]); \
    }

    float4 ra[4];
#pragma unroll
    for (int i = 0; i < 4; ++i) ra[i] = *(const float4*)(xg + 4 * i);
    LOAD_B(0, 0); cp_commit();
    STS_A(0, ra);
#pragma unroll
    for (int i = 0; i < 4; ++i) ra[i] = *(const float4*)(xg + BK + 4 * i);

    float acc[2][8][4];
#pragma unroll
    for (int mi = 0; mi < 2; ++mi)
#pragma unroll
        for (int ni = 0; ni < 8; ++ni)
#pragma unroll
            for (int c = 0; c < 4; ++c) acc[mi][ni][c] = 0.f;

    const uint32_t aoff = ((lane & 7) + ((lane >> 3) & 1) * 8) * 80 + ((lane >> 4) & 1) * 16;
    const uint32_t* s32m = (const uint32_t*)smem;
    const int bword0 = (ST_BH + (wn * 64 + (lane >> 2)) * 80 + (lane & 3) * 4) >> 2;
    const float S = 3.0517578125e-05f;   // 2^-15

    for (int kt = 0; kt < KT; ++kt) {
        cp_wait0();
        __syncthreads();
        if (kt + 1 < KT) { LOAD_B((kt + 1) & 1, kt + 1); cp_commit(); STS_A((kt + 1) & 1, ra); }
        if (kt + 2 < KT) {
#pragma unroll
            for (int i = 0; i < 4; ++i) ra[i] = *(const float4*)(xg + (kt + 2) * BK + 4 * i);
        }
        const uint32_t bs = sb + (kt & 1) * STG;
        const int sw = ((kt & 1) * STG) >> 2;

        // fp16 hi*hi
#pragma unroll
        for (int kk = 0; kk < 2; ++kk) {
            uint32_t ah[2][4];
#pragma unroll
            for (int mi = 0; mi < 2; ++mi)
                ldm4(ah[mi], bs + ST_AH + (wm * 32 + mi * 16) * 80 + kk * 32 + aoff);
#pragma unroll
            for (int ni = 0; ni < 8; ++ni) {
                int bo = sw + bword0 + (ni * 8 * 80 + kk * 32) / 4;
                uint32_t bh[2] = { s32m[bo], s32m[bo + 4] };
#pragma unroll
                for (int mi = 0; mi < 2; ++mi) mma_f16(acc[mi][ni], ah[mi], bh);
            }
        }
        // int8 cross terms
        {
            const uint32_t kwl = (lane & 3) * 8, kwh = kwl + 32;
            uint2 q[2][4];
#pragma unroll
            for (int mi = 0; mi < 2; ++mi) {
                uint32_t r0 = bs + ST_A8 + (wm * 32 + mi * 16 + (lane >> 2)) * 80;
                q[mi][0] = lds64(r0 + kwl);        q[mi][1] = lds64(r0 + 8 * 80 + kwl);
                q[mi][2] = lds64(r0 + kwh);        q[mi][3] = lds64(r0 + 8 * 80 + kwh);
            }
#pragma unroll
            for (int ni = 0; ni < 8; ++ni) {
                uint32_t nr = bs + ST_B8 + (wn * 64 + ni * 8 + (lane >> 2)) * 80;
                uint2 p0 = lds64(nr + kwl), p1 = lds64(nr + kwh);
#pragma unroll
                for (int mi = 0; mi < 2; ++mi) {
                    int t4[4] = {0, 0, 0, 0};
                    mma_s8(t4, q[mi][0].x, q[mi][1].x, q[mi][2].x, q[mi][3].x, p0.y, p1.y);
                    mma_s8(t4, q[mi][0].y, q[mi][1].y, q[mi][2].y, q[mi][3].y, p0.x, p1.x);
#pragma unroll
                    for (int c = 0; c < 4; ++c)
                        acc[mi][ni][c] = fmaf((float)t4[c], S, acc[mi][ni][c]);
                }
            }
        }
    }

    // epilogue
    float part[4][NEXP];
#pragma unroll
    for (int p = 0; p < 4; ++p)
#pragma unroll
        for (int e = 0; e < NEXP; ++e) part[p][e] = 0.f;
    const float isc = 1.0f / 1024.0f;
#pragma unroll
    for (int mi = 0; mi < 2; ++mi)
#pragma unroll
        for (int h = 0; h < 2; ++h) {
            const int pi = mi * 2 + h;
#pragma unroll
            for (int ni = 0; ni < 8; ++ni) {
                int nl = wn * 64 + ni * 8 + (lane & 3) * 2;
                float v0 = acc[mi][ni][h * 2] * isc + b1s[nl];
                float v1 = acc[mi][ni][h * 2 + 1] * isc + b1s[nl + 1];
                float g0 = 0.5f * v0 * (1.0f + erff(v0 * 0.7071067811865475f));
                float g1 = 0.5f * v1 * (1.0f + erff(v1 * 0.7071067811865475f));
                const float* wr = w2s + nl * NEXP;
#pragma unroll
                for (int e = 0; e < NEXP; ++e)
                    part[pi][e] = fmaf(g0, wr[e], fmaf(g1, wr[NEXP + e], part[pi][e]));
            }
        }
#pragma unroll
    for (int p = 0; p < 4; ++p)
#pragma unroll
        for (int e = 0; e < NEXP; ++e) {
            float v = part[p][e];
            v += __shfl_xor_sync(0xffffffffu, v, 1);
            v += __shfl_xor_sync(0xffffffffu, v, 2);
            part[p][e] = v;
        }
    if ((lane & 3) == 0)
#pragma unroll
        for (int p = 0; p < 4; ++p) {
            int r = m0 + wm * 32 + (p >> 1) * 16 + (p & 1) * 8 + (lane >> 2);
#pragma unroll
            for (int e = 0; e < NEXP; ++e)
                atomicAdd(&ew[(size_t)r * NEXP + e], part[p][e]);
        }
}

// ---------- kernel 2: top-2 + masks + usage; flag near-ties ----------
__global__ void topk_kernel(const float* __restrict__ ew, float* __restrict__ masks, int M) {
    __shared__ float su[NEXP];
    __shared__ int sc;
    const int t = threadIdx.x;
    if (t < NEXP) su[t] = 0.f;
    if (t == 0)   sc = 0;
    __syncthreads();
    const int tok = blockIdx.x * blockDim.x + t;
    if (tok < M) {
        float v[NEXP];
        float4 a = *(const float4*)(ew + (size_t)tok * NEXP);
        float4 b = *(const float4*)(ew + (size_t)tok * NEXP + 4);
        v[0]=a.x; v[1]=a.y; v[2]=a.z; v[3]=a.w; v[4]=b.x; v[5]=b.y; v[6]=b.z; v[7]=b.w;
        int i1 = 0; float m1 = v[0];
#pragma unroll
        for (int e = 1; e < NEXP; ++e) if (v[e] > m1) { m1 = v[e]; i1 = e; }
        int i2 = -1; float m2 = -3.4e38f;
#pragma unroll
        for (int e = 0; e < NEXP; ++e) if (e != i1 && v[e] > m2) { m2 = v[e]; i2 = e; }
        float m3 = -3.4e38f;
#pragma unroll
        for (int e = 0; e < NEXP; ++e) if (e != i1 && e != i2 && v[e] > m3) m3 = v[e];
        if (m2 - m3 < GAP_TH) {
            int idx = atomicAdd(&g_nflag, 1);
            if (idx < MAXFLAG) g_list[idx] = tok;
        } else {
            float ex = expf(m2 - m1);
            float p1 = 1.f / (1.f + ex), p2 = ex / (1.f + ex);
            float o[NEXP];
#pragma unroll
            for (int e = 0; e < NEXP; ++e) o[e] = (e == i1) ? p1 : ((e == i2) ? p2 : 0.f);
            *(float4*)(masks + (size_t)tok * NEXP)     = make_float4(o[0], o[1], o[2], o[3]);
            *(float4*)(masks + (size_t)tok * NEXP + 4) = make_float4(o[4], o[5], o[6], o[7]);
            atomicAdd(&su[i1], p1);
            atomicAdd(&su[i2], p2);
            atomicAdd(&sc, (p1 > 0.f) + (p2 > 0.f));
        }
    }
    __syncthreads();
    if (t < NEXP) atomicAdd(&g_usage[t], su[t]);
    if (t == 0)   atomicAdd(&g_count, sc);
}

// ---------- kernel 3: exact repair of flagged tokens + losses ----------
__global__ void repair_kernel(const float* __restrict__ x, const float* __restrict__ b1,
                              const float* __restrict__ w2, float* __restrict__ masks,
                              float* __restrict__ tail, int M) {
    __shared__ float xs[HDIM];
    __shared__ float red[8][NEXP];
    __shared__ float sew[NEXP];
    const int t = threadIdx.x, w = t >> 5, lane = t & 31;
    const int nf = min(g_nflag, MAXFLAG);
    for (int it = blockIdx.x; it < nf; it += gridDim.x) {
        const int tok = g_list[it];
        for (int i = t; i < HDIM; i += 256) xs[i] = x[(size_t)tok * HDIM + i];
        __syncthreads();
        float part[NEXP];
#pragma unroll
        for (int e = 0; e < NEXP; ++e) part[e] = 0.f;
        for (int nn = 0; nn < NDIM / 256; ++nn) {
            const int n = t + nn * 256;
            const __half* whp = g_wh + (size_t)n * HDIM;
            const __half* wlp = g_wl + (size_t)n * HDIM;
            float acc = 0.f;
            for (int k = 0; k < HDIM; k += 2) {
                float2 hf = __half22float2(*(const __half2*)(whp + k));
                float2 lf = __half22float2(*(const __half2*)(wlp + k));
                acc = fmaf(xs[k],     hf.x + lf.x, acc);
                acc = fmaf(xs[k + 1], hf.y + lf.y, acc);
            }
            float v = acc * (1.0f / 1024.0f) + b1[n];
            float g = 0.5f * v * (1.0f + erff(v * 0.7071067811865475f));
#pragma unroll
            for (int e = 0; e < NEXP; ++e) part[e] = fmaf(g, w2[n * NEXP + e], part[e]);
        }
#pragma unroll
        for (int e = 0; e < NEXP; ++e) {
            float v = part[e];
#pragma unroll
            for (int s = 16; s > 0; s >>= 1) v += __shfl_xor_sync(0xffffffffu, v, s);
            if (lane == 0) red[w][e] = v;
        }
        __syncthreads();
        if (t < NEXP) {
            float s = 0.f;
#pragma unroll
            for (int ww = 0; ww < 8; ++ww) s += red[ww][t];
            sew[t] = s;
        }
        __syncthreads();
        if (t == 0) {
            float v[NEXP];
#pragma unroll
            for (int e = 0; e < NEXP; ++e) v[e] = sew[e];
            int i1 = 0; float m1 = v[0];
#pragma unroll
            for (int e = 1; e < NEXP; ++e) if (v[e] > m1) { m1 = v[e]; i1 = e; }
            int i2 = -1; float m2 = -3.4e38f;
#pragma unroll
            for (int e = 0; e < NEXP; ++e) if (e != i1 && v[e] > m2) { m2 = v[e]; i2 = e; }
            float ex = expf(m2 - m1);
            float p1 = 1.f / (1.f + ex), p2 = ex / (1.f + ex);
#pragma unroll
            for (int e = 0; e < NEXP; ++e)
                masks[(size_t)tok * NEXP + e] = (e == i1) ? p1 : ((e == i2) ? p2 : 0.f);
            atomicAdd(&g_usage[i1], p1);
            atomicAdd(&g_usage[i2], p2);
            atomicAdd(&g_count, (p1 > 0.f) + (p2 > 0.f));
        }
        __syncthreads();
    }
    __threadfence();
    __syncthreads();
    if (t == 0 && atomicAdd(&g_done, 1) == (int)gridDim.x - 1) {
        __threadfence();
        float u[NEXP], s = 0.f;
#pragma unroll
        for (int e = 0; e < NEXP; ++e) { u[e] = g_usage[e]; s += u[e]; }
        float lb = 0.f;
#pragma unroll
        for (int e = 0; e < NEXP; ++e) {
            float un = u[e] / s;
            tail[1 + e] = un;
            float d = un - 0.125f;
            lb += d * d;
        }
        lb *= (1.f / 8.f);
        tail[0] = lb + 0.1f * (((float)g_count / (float)M) * 0.5f);
    }
}

// ---------- launch ----------
extern "C" void kernel_launch(void* const* d_in, const int* in_sizes, int n_in,
                              void* d_out, int out_size) {
    const float* x  = (const float*)d_in[0];
    const float* w1 = (const float*)d_in[1];
    const float* b1 = (const float*)d_in[2];
    const float* w2 = (const float*)d_in[3];
    const float* b2 = (const float*)d_in[4];
    float* out   = (float*)d_out;
    const int M  = in_sizes[0] / HDIM;
    float* ew    = out;
    float* masks = out + (size_t)M * NEXP;
    float* tail  = out + (size_t)2 * M * NEXP;

    cudaFuncSetAttribute(gemm_kernel, cudaFuncAttributeMaxDynamicSharedMemorySize, SMEM_DYN);

    pre_kernel<<<2048 + (M * NEXP + 255) / 256, 256>>>(w1, ew, b2);
    gemm_kernel<<<dim3(NDIM / BN, M / BM), 256, SMEM_DYN>>>(x, b1, w2, ew);
    topk_kernel<<<(M + 255) / 256, 256>>>(ew, masks, M);
    repair_kernel<<<64, 256>>>(x, b1, w2, masks, tail, M);
}

// round 8
// speedup vs baseline: 2.6267x; 2.6267x over previous
#include <cuda_runtime.h>
#include <cuda_fp16.h>
#include <math.h>
#include <stdint.h>

#define HDIM 1024
#define NDIM 2048
#define NEXP 8
#define MTOK 16384
#define BM 128
#define BN 128
#define BK 32
#define KT (HDIM / BK)
#define GAP_TH 8e-4f
#define MAXFLAG 8192

#define ST_AH 0
#define ST_BH 10240
#define ST_BL 20480
#define STG   30720
#define OFF_W2 (2 * STG)                 // 61440
#define OFF_B1 (OFF_W2 + BN * NEXP * 4)  // 65536
#define SMEM_DYN (OFF_B1 + BN * 4)       // 66048 (x2 CTAs = 132KB)

__device__ __half g_wh[NDIM * HDIM];     // w1^T * 1024, hi
__device__ __half g_wl[NDIM * HDIM];     // lo (exact residual)
__device__ float  g_ewfix[MAXFLAG * NEXP];
__device__ float  g_usage[NEXP];
__device__ int    g_count, g_nflag;
__device__ int    g_list[MAXFLAG];

__device__ __forceinline__ uint32_t smem_u32(const void* p) {
    uint32_t a;
    asm("{ .reg .u64 t; cvta.to.shared.u64 t, %1; cvt.u32.u64 %0, t; }" : "=r"(a) : "l"(p));
    return a;
}
__device__ __forceinline__ void cp16(uint32_t s, const void* g) {
    asm volatile("cp.async.cg.shared.global [%0], [%1], 16;" :: "r"(s), "l"(g));
}
__device__ __forceinline__ void cp_commit() { asm volatile("cp.async.commit_group;" ::: "memory"); }
__device__ __forceinline__ void cp_wait0()  { asm volatile("cp.async.wait_group 0;" ::: "memory"); }
__device__ __forceinline__ void ldm4(uint32_t* r, uint32_t a) {
    asm volatile("ldmatrix.sync.aligned.m8n8.x4.shared.b16 {%0,%1,%2,%3}, [%4];"
                 : "=r"(r[0]), "=r"(r[1]), "=r"(r[2]), "=r"(r[3]) : "r"(a));
}
__device__ __forceinline__ void mma(float* c, const uint32_t* a, const uint32_t* b) {
    asm volatile("mma.sync.aligned.m16n8k16.row.col.f32.f16.f16.f32 "
                 "{%0,%1,%2,%3}, {%4,%5,%6,%7}, {%8,%9}, {%0,%1,%2,%3};"
                 : "+f"(c[0]), "+f"(c[1]), "+f"(c[2]), "+f"(c[3])
                 : "r"(a[0]), "r"(a[1]), "r"(a[2]), "r"(a[3]), "r"(b[0]), "r"(b[1]));
}

// ---------- kernel 0: w1^T split (fp16 hi/lo) + init ----------
__global__ void pre_kernel(const float* __restrict__ w1, float* __restrict__ ew,
                           const float* __restrict__ b2) {
    __shared__ float tile[32][33];
    const int b = blockIdx.x, t = threadIdx.x;
    if (b < 2048) {
        const int nb = (b & 63) * 32, kb = (b >> 6) * 32;
        const int tx = t & 31, ty = t >> 5;
#pragma unroll
        for (int i = 0; i < 4; ++i)
            tile[ty + i * 8][tx] = w1[(size_t)(kb + ty + i * 8) * NDIM + nb + tx];
        __syncthreads();
#pragma unroll
        for (int i = 0; i < 4; ++i) {
            int row = ty + i * 8;
            float v = tile[tx][row] * 1024.0f;
            __half h = __float2half_rn(v);
            __half l = __float2half_rn(v - __half2float(h));
            size_t o = (size_t)(nb + row) * HDIM + kb + tx;
            g_wh[o] = h; g_wl[o] = l;
        }
    } else {
        const int i = (b - 2048) * 256 + t;
        if (i < MTOK * NEXP) ew[i] = b2[i & 7];
        if (b == 2048) {
            if (t < NEXP) g_usage[t] = 0.f;
            if (t == 0) { g_count = 0; g_nflag = 0; }
        }
    }
}

// ---------- kernel 1: GEMM (ah*(bh+bl)) + GELU + GEMM2 ----------
__global__ __launch_bounds__(256, 2)
void gemm_kernel(const float* __restrict__ x, const float* __restrict__ b1,
                 const float* __restrict__ w2, float* __restrict__ ew) {
    extern __shared__ char smem[];
    const uint32_t sb = smem_u32(smem);
    const int t = threadIdx.x, w = t >> 5, lane = t & 31;
    const int wm = w & 3, wn = w >> 2;
    const int n0 = blockIdx.x * BN, m0 = blockIdx.y * BM;

    float* w2s = (float*)(smem + OFF_W2);
    float* b1s = (float*)(smem + OFF_B1);
    for (int i = t; i < BN * NEXP; i += 256) w2s[i] = w2[(size_t)n0 * NEXP + i];
    for (int i = t; i < BN; i += 256)        b1s[i] = b1[n0 + i];

    const int rA = t >> 1;
    const float* xg = x + (size_t)(m0 + rA) * HDIM + (t & 1) * 16;
    const size_t gb0 = (size_t)(n0 + rA) * HDIM;

#define LOAD_B(stg, kt_)                                                     \
    {                                                                        \
        uint32_t _bs = sb + (stg) * STG + rA * 80;                           \
        size_t _kb = gb0 + (size_t)(kt_) * BK;                               \
        _Pragma("unroll")                                                    \
        for (int j = 0; j < 2; ++j) {                                        \
            int c16 = (t & 1) * 2 + j;                                       \
            cp16(_bs + ST_BH + c16 * 16, g_wh + _kb + c16 * 8);              \
            cp16(_bs + ST_BL + c16 * 16, g_wl + _kb + c16 * 8);              \
        }                                                                    \
    }

#define STS_A(stg, ra_)                                                      \
    {                                                                        \
        uint32_t hws[8];                                                     \
        _Pragma("unroll")                                                    \
        for (int wi = 0; wi < 4; ++wi) {                                     \
            const float* fp = (const float*)&(ra_)[wi];                      \
            __half2 p01 = __halves2half2(__float2half_rn(fp[0]),             \
                                         __float2half_rn(fp[1]));            \
            __half2 p23 = __halves2half2(__float2half_rn(fp[2]),             \
                                         __float2half_rn(fp[3]));            \
            hws[wi*2] = *(uint32_t*)&p01; hws[wi*2+1] = *(uint32_t*)&p23;    \
        }                                                                    \
        char* _p = smem + (stg) * STG + ST_AH + rA * 80 + (t & 1) * 32;      \
        *(uint4*)(_p)      = make_uint4(hws[0], hws[1], hws[2], hws[3]);     \
        *(uint4*)(_p + 16) = make_uint4(hws[4], hws[5], hws[6], hws[7]);     \
    }

    float4 ra[4];
#pragma unroll
    for (int i = 0; i < 4; ++i) ra[i] = *(const float4*)(xg + 4 * i);
    LOAD_B(0, 0); cp_commit();
    STS_A(0, ra);
#pragma unroll
    for (int i = 0; i < 4; ++i) ra[i] = *(const float4*)(xg + BK + 4 * i);

    float acc[2][8][4];
#pragma unroll
    for (int mi = 0; mi < 2; ++mi)
#pragma unroll
        for (int ni = 0; ni < 8; ++ni)
#pragma unroll
            for (int c = 0; c < 4; ++c) acc[mi][ni][c] = 0.f;

    const uint32_t aoff = ((lane & 7) + ((lane >> 3) & 1) * 8) * 80 + ((lane >> 4) & 1) * 16;
    const uint32_t* s32m = (const uint32_t*)smem;
    const int bword0 = (ST_BH + (wn * 64 + (lane >> 2)) * 80 + (lane & 3) * 4) >> 2;
    const int BLOFF = (ST_BL - ST_BH) >> 2;

    for (int kt = 0; kt < KT; ++kt) {
        cp_wait0();
        __syncthreads();
        if (kt + 1 < KT) { LOAD_B((kt + 1) & 1, kt + 1); cp_commit(); STS_A((kt + 1) & 1, ra); }
        if (kt + 2 < KT) {
#pragma unroll
            for (int i = 0; i < 4; ++i) ra[i] = *(const float4*)(xg + (kt + 2) * BK + 4 * i);
        }
        const uint32_t bs = sb + (kt & 1) * STG;
        const int sw = ((kt & 1) * STG) >> 2;
#pragma unroll
        for (int kk = 0; kk < 2; ++kk) {
            uint32_t ah[2][4];
#pragma unroll
            for (int mi = 0; mi < 2; ++mi)
                ldm4(ah[mi], bs + ST_AH + (wm * 32 + mi * 16) * 80 + kk * 32 + aoff);
#pragma unroll
            for (int ni = 0; ni < 8; ++ni) {
                int bo = sw + bword0 + (ni * 8 * 80 + kk * 32) / 4;
                uint32_t bh[2] = { s32m[bo], s32m[bo + 4] };
                uint32_t bl[2] = { s32m[bo + BLOFF], s32m[bo + BLOFF + 4] };
#pragma unroll
                for (int mi = 0; mi < 2; ++mi) {
                    mma(acc[mi][ni], ah[mi], bh);
                    mma(acc[mi][ni], ah[mi], bl);
                }
            }
        }
    }

    // epilogue
    float part[4][NEXP];
#pragma unroll
    for (int p = 0; p < 4; ++p)
#pragma unroll
        for (int e = 0; e < NEXP; ++e) part[p][e] = 0.f;
    const float isc = 1.0f / 1024.0f;
#pragma unroll
    for (int mi = 0; mi < 2; ++mi)
#pragma unroll
        for (int h = 0; h < 2; ++h) {
            const int pi = mi * 2 + h;
#pragma unroll
            for (int ni = 0; ni < 8; ++ni) {
                int nl = wn * 64 + ni * 8 + (lane & 3) * 2;
                float v0 = acc[mi][ni][h * 2] * isc + b1s[nl];
                float v1 = acc[mi][ni][h * 2 + 1] * isc + b1s[nl + 1];
                float g0 = 0.5f * v0 * (1.0f + erff(v0 * 0.7071067811865475f));
                float g1 = 0.5f * v1 * (1.0f + erff(v1 * 0.7071067811865475f));
                const float* wr = w2s + nl * NEXP;
#pragma unroll
                for (int e = 0; e < NEXP; ++e)
                    part[pi][e] = fmaf(g0, wr[e], fmaf(g1, wr[NEXP + e], part[pi][e]));
            }
        }
#pragma unroll
    for (int p = 0; p < 4; ++p)
#pragma unroll
        for (int e = 0; e < NEXP; ++e) {
            float v = part[p][e];
            v += __shfl_xor_sync(0xffffffffu, v, 1);
            v += __shfl_xor_sync(0xffffffffu, v, 2);
            part[p][e] = v;
        }
    if ((lane & 3) == 0)
#pragma unroll
        for (int p = 0; p < 4; ++p) {
            int r = m0 + wm * 32 + (p >> 1) * 16 + (p & 1) * 8 + (lane >> 2);
#pragma unroll
            for (int e = 0; e < NEXP; ++e)
                atomicAdd(&ew[(size_t)r * NEXP + e], part[p][e]);
        }
}

// ---------- kernel 2: top-2 + masks + usage; flag near top2/top3 ties ----------
__global__ void topk_kernel(const float* __restrict__ ew, float* __restrict__ masks,
                            const float* __restrict__ b2, int M) {
    __shared__ float su[NEXP];
    __shared__ int sc;
    const int t = threadIdx.x;
    if (t < NEXP) su[t] = 0.f;
    if (t == 0)   sc = 0;
    __syncthreads();
    const int tok = blockIdx.x * blockDim.x + t;
    if (tok < M) {
        float v[NEXP];
        float4 a = *(const float4*)(ew + (size_t)tok * NEXP);
        float4 b = *(const float4*)(ew + (size_t)tok * NEXP + 4);
        v[0]=a.x; v[1]=a.y; v[2]=a.z; v[3]=a.w; v[4]=b.x; v[5]=b.y; v[6]=b.z; v[7]=b.w;
        int i1 = 0; float m1 = v[0];
#pragma unroll
        for (int e = 1; e < NEXP; ++e) if (v[e] > m1) { m1 = v[e]; i1 = e; }
        int i2 = -1; float m2 = -3.4e38f;
#pragma unroll
        for (int e = 0; e < NEXP; ++e) if (e != i1 && v[e] > m2) { m2 = v[e]; i2 = e; }
        float m3 = -3.4e38f;
#pragma unroll
        for (int e = 0; e < NEXP; ++e) if (e != i1 && e != i2 && v[e] > m3) m3 = v[e];
        bool flagged = false;
        if (m2 - m3 < GAP_TH) {
            int idx = atomicAdd(&g_nflag, 1);
            if (idx < MAXFLAG) {
                flagged = true;
                g_list[idx] = tok;
#pragma unroll
                for (int e = 0; e < NEXP; ++e) g_ewfix[idx * NEXP + e] = b2[e];
            }
        }
        if (!flagged) {
            float ex = expf(m2 - m1);
            float p1 = 1.f / (1.f + ex), p2 = ex / (1.f + ex);
            float o[NEXP];
#pragma unroll
            for (int e = 0; e < NEXP; ++e) o[e] = (e == i1) ? p1 : ((e == i2) ? p2 : 0.f);
            *(float4*)(masks + (size_t)tok * NEXP)     = make_float4(o[0], o[1], o[2], o[3]);
            *(float4*)(masks + (size_t)tok * NEXP + 4) = make_float4(o[4], o[5], o[6], o[7]);
            atomicAdd(&su[i1], p1);
            atomicAdd(&su[i2], p2);
            atomicAdd(&sc, (p1 > 0.f) + (p2 > 0.f));
        }
    }
    __syncthreads();
    if (t < NEXP) atomicAdd(&g_usage[t], su[t]);
    if (t == 0)   atomicAdd(&g_count, sc);
}

// ---------- kernel 3a: recompute flagged rows exactly (w read once total) ----------
__global__ void repairA_kernel(const float* __restrict__ x, const float* __restrict__ b1,
                               const float* __restrict__ w2) {
    __shared__ float ws[8][HDIM];    // 32 KB: this block's 8 n-rows, exact fp32
    __shared__ float xsm[HDIM];
    __shared__ float gsh[8];
    const int t = threadIdx.x, w = t >> 5, lane = t & 31;
    const int nb = blockIdx.x * 8;
    for (int i = t; i < 8 * HDIM; i += 256) {
        int row = i >> 10, k = i & 1023;
        size_t o = (size_t)(nb + row) * HDIM + k;
        ws[row][k] = (__half2float(g_wh[o]) + __half2float(g_wl[o])) * (1.0f / 1024.0f);
    }
    __syncthreads();
    const int nf = min(g_nflag, MAXFLAG);
    for (int it = 0; it < nf; ++it) {
        const int tok = g_list[it];
        for (int i = t; i < HDIM; i += 256) xsm[i] = x[(size_t)tok * HDIM + i];
        __syncthreads();
        float s = 0.f;
        const float* wr = ws[w];
#pragma unroll 8
        for (int k = lane * 32; k < lane * 32 + 32; ++k) s = fmaf(xsm[k], wr[k], s);
#pragma unroll
        for (int d = 16; d > 0; d >>= 1) s += __shfl_xor_sync(0xffffffffu, s, d);
        if (lane == 0) {
            float v = s + b1[nb + w];
            gsh[w] = 0.5f * v * (1.0f + erff(v * 0.7071067811865475f));
        }
        __syncthreads();
        if (t < NEXP) {
            float acc = 0.f;
#pragma unroll
            for (int ww = 0; ww < 8; ++ww) acc = fmaf(gsh[ww], w2[(nb + ww) * NEXP + t], acc);
            atomicAdd(&g_ewfix[it * NEXP + t], acc);
        }
        __syncthreads();
    }
}

// ---------- kernel 3b: flagged masks/usage + losses (single block) ----------
__global__ void repairB_kernel(float* __restrict__ masks, float* __restrict__ tail, int M) {
    __shared__ float su[NEXP];
    __shared__ int sc;
    const int t = threadIdx.x;
    if (t < NEXP) su[t] = 0.f;
    if (t == 0)   sc = 0;
    __syncthreads();
    const int nf = min(g_nflag, MAXFLAG);
    for (int it = t; it < nf; it += 256) {
        const int tok = g_list[it];
        float v[NEXP];
#pragma unroll
        for (int e = 0; e < NEXP; ++e) v[e] = g_ewfix[it * NEXP + e];
        int i1 = 0; float m1 = v[0];
#pragma unroll
        for (int e = 1; e < NEXP; ++e) if (v[e] > m1) { m1 = v[e]; i1 = e; }
        int i2 = -1; float m2 = -3.4e38f;
#pragma unroll
        for (int e = 0; e < NEXP; ++e) if (e != i1 && v[e] > m2) { m2 = v[e]; i2 = e; }
        float ex = expf(m2 - m1);
        float p1 = 1.f / (1.f + ex), p2 = ex / (1.f + ex);
        float o[NEXP];
#pragma unroll
        for (int e = 0; e < NEXP; ++e) o[e] = (e == i1) ? p1 : ((e == i2) ? p2 : 0.f);
        *(float4*)(masks + (size_t)tok * NEXP)     = make_float4(o[0], o[1], o[2], o[3]);
        *(float4*)(masks + (size_t)tok * NEXP + 4) = make_float4(o[4], o[5], o[6], o[7]);
        atomicAdd(&su[i1], p1);
        atomicAdd(&su[i2], p2);
        atomicAdd(&sc, (p1 > 0.f) + (p2 > 0.f));
    }
    __syncthreads();
    if (t == 0) {
        float u[NEXP], s = 0.f;
#pragma unroll
        for (int e = 0; e < NEXP; ++e) { u[e] = g_usage[e] + su[e]; s += u[e]; }
        float lb = 0.f;
#pragma unroll
        for (int e = 0; e < NEXP; ++e) {
            float un = u[e] / s;
            tail[1 + e] = un;
            float d = un - 0.125f;
            lb += d * d;
        }
        lb *= (1.f / 8.f);
        tail[0] = lb + 0.1f * (((float)(g_count + sc) / (float)M) * 0.5f);
    }
}

// ---------- launch ----------
extern "C" void kernel_launch(void* const* d_in, const int* in_sizes, int n_in,
                              void* d_out, int out_size) {
    const float* x  = (const float*)d_in[0];
    const float* w1 = (const float*)d_in[1];
    const float* b1 = (const float*)d_in[2];
    const float* w2 = (const float*)d_in[3];
    const float* b2 = (const float*)d_in[4];
    float* out   = (float*)d_out;
    const int M  = in_sizes[0] / HDIM;
    float* ew    = out;
    float* masks = out + (size_t)M * NEXP;
    float* tail  = out + (size_t)2 * M * NEXP;

    cudaFuncSetAttribute(gemm_kernel, cudaFuncAttributeMaxDynamicSharedMemorySize, SMEM_DYN);

    pre_kernel<<<2048 + (M * NEXP + 255) / 256, 256>>>(w1, ew, b2);
    gemm_kernel<<<dim3(NDIM / BN, M / BM), 256, SMEM_DYN>>>(x, b1, w2, ew);
    topk_kernel<<<(M + 255) / 256, 256>>>(ew, masks, b2, M);
    repairA_kernel<<<NDIM / 8, 256>>>(x, b1, w2);
    repairB_kernel<<<1, 256>>>(masks, tail, M);
}

// round 9
// speedup vs baseline: 3.8635x; 1.4709x over previous
#include <cuda_runtime.h>
#include <cuda_fp16.h>
#include <math.h>
#include <stdint.h>

#define HDIM 1024
#define NDIM 2048
#define NEXP 8
#define MTOK 16384
#define BM 128
#define BN 128
#define BK 32
#define KT (HDIM / BK)
#define GAP_TH 5e-4f
#define MAXFLAG 8192

#define ST_AH 0
#define ST_BH 10240
#define ST_BL 20480
#define STG   30720
#define OFF_W2 (2 * STG)
#define OFF_B1 (OFF_W2 + BN * NEXP * 4)
#define SMEM_DYN (OFF_B1 + BN * 4)

__device__ __half g_wh[NDIM * HDIM];
__device__ __half g_wl[NDIM * HDIM];
__device__ float  g_ewfix[MAXFLAG * NEXP];
__device__ float  g_usage[NEXP];
__device__ int    g_count, g_nflag;
__device__ int    g_list[MAXFLAG];

__device__ __forceinline__ uint32_t smem_u32(const void* p) {
    uint32_t a;
    asm("{ .reg .u64 t; cvta.to.shared.u64 t, %1; cvt.u32.u64 %0, t; }" : "=r"(a) : "l"(p));
    return a;
}
__device__ __forceinline__ void cp16(uint32_t s, const void* g) {
    asm volatile("cp.async.cg.shared.global [%0], [%1], 16;" :: "r"(s), "l"(g));
}
__device__ __forceinline__ void cp_commit() { asm volatile("cp.async.commit_group;" ::: "memory"); }
__device__ __forceinline__ void cp_wait0()  { asm volatile("cp.async.wait_group 0;" ::: "memory"); }
__device__ __forceinline__ void ldm4(uint32_t* r, uint32_t a) {
    asm volatile("ldmatrix.sync.aligned.m8n8.x4.shared.b16 {%0,%1,%2,%3}, [%4];"
                 : "=r"(r[0]), "=r"(r[1]), "=r"(r[2]), "=r"(r[3]) : "r"(a));
}
__device__ __forceinline__ void mma(float* c, const uint32_t* a, const uint32_t* b) {
    asm volatile("mma.sync.aligned.m16n8k16.row.col.f32.f16.f16.f32 "
                 "{%0,%1,%2,%3}, {%4,%5,%6,%7}, {%8,%9}, {%0,%1,%2,%3};"
                 : "+f"(c[0]), "+f"(c[1]), "+f"(c[2]), "+f"(c[3])
                 : "r"(a[0]), "r"(a[1]), "r"(a[2]), "r"(a[3]), "r"(b[0]), "r"(b[1]));
}

// ---------- kernel 0: w1^T split (fp16 hi/lo) + init ----------
__global__ void pre_kernel(const float* __restrict__ w1, float* __restrict__ ew,
                           const float* __restrict__ b2) {
    __shared__ float tile[32][33];
    const int b = blockIdx.x, t = threadIdx.x;
    if (b < 2048) {
        const int nb = (b & 63) * 32, kb = (b >> 6) * 32;
        const int tx = t & 31, ty = t >> 5;
#pragma unroll
        for (int i = 0; i < 4; ++i)
            tile[ty + i * 8][tx] = w1[(size_t)(kb + ty + i * 8) * NDIM + nb + tx];
        __syncthreads();
#pragma unroll
        for (int i = 0; i < 4; ++i) {
            int row = ty + i * 8;
            float v = tile[tx][row] * 1024.0f;
            __half h = __float2half_rn(v);
            __half l = __float2half_rn(v - __half2float(h));
            size_t o = (size_t)(nb + row) * HDIM + kb + tx;
            g_wh[o] = h; g_wl[o] = l;
        }
    } else {
        const int i = (b - 2048) * 256 + t;
        if (i < MTOK * NEXP) ew[i] = b2[i & 7];
        if (b == 2048) {
            if (t < NEXP) g_usage[t] = 0.f;
            if (t == 0) { g_count = 0; g_nflag = 0; }
        }
    }
}

// ---------- kernel 1: GEMM (ah*(bh+bl)) + GELU + GEMM2 ----------
__global__ __launch_bounds__(256, 2)
void gemm_kernel(const float* __restrict__ x, const float* __restrict__ b1,
                 const float* __restrict__ w2, float* __restrict__ ew) {
    extern __shared__ char smem[];
    const uint32_t sb = smem_u32(smem);
    const int t = threadIdx.x, w = t >> 5, lane = t & 31;
    const int wm = w & 3, wn = w >> 2;
    const int n0 = blockIdx.x * BN, m0 = blockIdx.y * BM;

    float* w2s = (float*)(smem + OFF_W2);
    float* b1s = (float*)(smem + OFF_B1);
    for (int i = t; i < BN * NEXP; i += 256) w2s[i] = w2[(size_t)n0 * NEXP + i];
    for (int i = t; i < BN; i += 256)        b1s[i] = b1[n0 + i];

    const int rA = t >> 1;
    const float* xg = x + (size_t)(m0 + rA) * HDIM + (t & 1) * 16;
    const size_t gb0 = (size_t)(n0 + rA) * HDIM;

#define LOAD_B(stg, kt_)                                                     \
    {                                                                        \
        uint32_t _bs = sb + (stg) * STG + rA * 80;                           \
        size_t _kb = gb0 + (size_t)(kt_) * BK;                               \
        _Pragma("unroll")                                                    \
        for (int j = 0; j < 2; ++j) {                                        \
            int c16 = (t & 1) * 2 + j;                                       \
            cp16(_bs + ST_BH + c16 * 16, g_wh + _kb + c16 * 8);              \
            cp16(_bs + ST_BL + c16 * 16, g_wl + _kb + c16 * 8);              \
        }                                                                    \
    }

#define STS_A(stg, ra_)                                                      \
    {                                                                        \
        uint32_t hws[8];                                                     \
        _Pragma("unroll")                                                    \
        for (int wi = 0; wi < 4; ++wi) {                                     \
            const float* fp = (const float*)&(ra_)[wi];                      \
            __half2 p01 = __halves2half2(__float2half_rn(fp[0]),             \
                                         __float2half_rn(fp[1]));            \
            __half2 p23 = __halves2half2(__float2half_rn(fp[2]),             \
                                         __float2half_rn(fp[3]));            \
            hws[wi*2] = *(uint32_t*)&p01; hws[wi*2+1] = *(uint32_t*)&p23;    \
        }                                                                    \
        char* _p = smem + (stg) * STG + ST_AH + rA * 80 + (t & 1) * 32;      \
        *(uint4*)(_p)      = make_uint4(hws[0], hws[1], hws[2], hws[3]);     \
        *(uint4*)(_p + 16) = make_uint4(hws[4], hws[5], hws[6], hws[7]);     \
    }

    float4 ra[4];
#pragma unroll
    for (int i = 0; i < 4; ++i) ra[i] = *(const float4*)(xg + 4 * i);
    LOAD_B(0, 0); cp_commit();
    STS_A(0, ra);
#pragma unroll
    for (int i = 0; i < 4; ++i) ra[i] = *(const float4*)(xg + BK + 4 * i);

    float acc[2][8][4];
#pragma unroll
    for (int mi = 0; mi < 2; ++mi)
#pragma unroll
        for (int ni = 0; ni < 8; ++ni)
#pragma unroll
            for (int c = 0; c < 4; ++c) acc[mi][ni][c] = 0.f;

    const uint32_t aoff = ((lane & 7) + ((lane >> 3) & 1) * 8) * 80 + ((lane >> 4) & 1) * 16;
    const uint32_t* s32m = (const uint32_t*)smem;
    const int bword0 = (ST_BH + (wn * 64 + (lane >> 2)) * 80 + (lane & 3) * 4) >> 2;
    const int BLOFF = (ST_BL - ST_BH) >> 2;

    for (int kt = 0; kt < KT; ++kt) {
        cp_wait0();
        __syncthreads();
        if (kt + 1 < KT) { LOAD_B((kt + 1) & 1, kt + 1); cp_commit(); STS_A((kt + 1) & 1, ra); }
        if (kt + 2 < KT) {
#pragma unroll
            for (int i = 0; i < 4; ++i) ra[i] = *(const float4*)(xg + (kt + 2) * BK + 4 * i);
        }
        const uint32_t bs = sb + (kt & 1) * STG;
        const int sw = ((kt & 1) * STG) >> 2;
#pragma unroll
        for (int kk = 0; kk < 2; ++kk) {
            uint32_t ah[2][4];
#pragma unroll
            for (int mi = 0; mi < 2; ++mi)
                ldm4(ah[mi], bs + ST_AH + (wm * 32 + mi * 16) * 80 + kk * 32 + aoff);
#pragma unroll
            for (int ni = 0; ni < 8; ++ni) {
                int bo = sw + bword0 + (ni * 8 * 80 + kk * 32) / 4;
                uint32_t bh[2] = { s32m[bo], s32m[bo + 4] };
                uint32_t bl[2] = { s32m[bo + BLOFF], s32m[bo + BLOFF + 4] };
#pragma unroll
                for (int mi = 0; mi < 2; ++mi) {
                    mma(acc[mi][ni], ah[mi], bh);
                    mma(acc[mi][ni], ah[mi], bl);
                }
            }
        }
    }

    float part[4][NEXP];
#pragma unroll
    for (int p = 0; p < 4; ++p)
#pragma unroll
        for (int e = 0; e < NEXP; ++e) part[p][e] = 0.f;
    const float isc = 1.0f / 1024.0f;
#pragma unroll
    for (int mi = 0; mi < 2; ++mi)
#pragma unroll
        for (int h = 0; h < 2; ++h) {
            const int pi = mi * 2 + h;
#pragma unroll
            for (int ni = 0; ni < 8; ++ni) {
                int nl = wn * 64 + ni * 8 + (lane & 3) * 2;
                float v0 = acc[mi][ni][h * 2] * isc + b1s[nl];
                float v1 = acc[mi][ni][h * 2 + 1] * isc + b1s[nl + 1];
                float g0 = 0.5f * v0 * (1.0f + erff(v0 * 0.7071067811865475f));
                float g1 = 0.5f * v1 * (1.0f + erff(v1 * 0.7071067811865475f));
                const float* wr = w2s + nl * NEXP;
#pragma unroll
                for (int e = 0; e < NEXP; ++e)
                    part[pi][e] = fmaf(g0, wr[e], fmaf(g1, wr[NEXP + e], part[pi][e]));
            }
        }
#pragma unroll
    for (int p = 0; p < 4; ++p)
#pragma unroll
        for (int e = 0; e < NEXP; ++e) {
            float v = part[p][e];
            v += __shfl_xor_sync(0xffffffffu, v, 1);
            v += __shfl_xor_sync(0xffffffffu, v, 2);
            part[p][e] = v;
        }
    if ((lane & 3) == 0)
#pragma unroll
        for (int p = 0; p < 4; ++p) {
            int r = m0 + wm * 32 + (p >> 1) * 16 + (p & 1) * 8 + (lane >> 2);
#pragma unroll
            for (int e = 0; e < NEXP; ++e)
                atomicAdd(&ew[(size_t)r * NEXP + e], part[p][e]);
        }
}

// ---------- kernel 2: top-2 + masks + usage; flag near top2/top3 ties ----------
__global__ void topk_kernel(const float* __restrict__ ew, float* __restrict__ masks,
                            const float* __restrict__ b2, int M) {
    __shared__ float su[NEXP];
    __shared__ int sc;
    const int t = threadIdx.x;
    if (t < NEXP) su[t] = 0.f;
    if (t == 0)   sc = 0;
    __syncthreads();
    const int tok = blockIdx.x * blockDim.x + t;
    if (tok < M) {
        float v[NEXP];
        float4 a = *(const float4*)(ew + (size_t)tok * NEXP);
        float4 b = *(const float4*)(ew + (size_t)tok * NEXP + 4);
        v[0]=a.x; v[1]=a.y; v[2]=a.z; v[3]=a.w; v[4]=b.x; v[5]=b.y; v[6]=b.z; v[7]=b.w;
        int i1 = 0; float m1 = v[0];
#pragma unroll
        for (int e = 1; e < NEXP; ++e) if (v[e] > m1) { m1 = v[e]; i1 = e; }
        int i2 = -1; float m2 = -3.4e38f;
#pragma unroll
        for (int e = 0; e < NEXP; ++e) if (e != i1 && v[e] > m2) { m2 = v[e]; i2 = e; }
        float m3 = -3.4e38f;
#pragma unroll
        for (int e = 0; e < NEXP; ++e) if (e != i1 && e != i2 && v[e] > m3) m3 = v[e];
        bool flagged = false;
        if (m2 - m3 < GAP_TH) {
            int idx = atomicAdd(&g_nflag, 1);
            if (idx < MAXFLAG) {
                flagged = true;
                g_list[idx] = tok;
#pragma unroll
                for (int e = 0; e < NEXP; ++e) g_ewfix[idx * NEXP + e] = b2[e];
            }
        }
        if (!flagged) {
            float ex = expf(m2 - m1);
            float p1 = 1.f / (1.f + ex), p2 = ex / (1.f + ex);
            float o[NEXP];
#pragma unroll
            for (int e = 0; e < NEXP; ++e) o[e] = (e == i1) ? p1 : ((e == i2) ? p2 : 0.f);
            *(float4*)(masks + (size_t)tok * NEXP)     = make_float4(o[0], o[1], o[2], o[3]);
            *(float4*)(masks + (size_t)tok * NEXP + 4) = make_float4(o[4], o[5], o[6], o[7]);
            atomicAdd(&su[i1], p1);
            atomicAdd(&su[i2], p2);
            atomicAdd(&sc, (p1 > 0.f) + (p2 > 0.f));
        }
    }
    __syncthreads();
    if (t < NEXP) atomicAdd(&g_usage[t], su[t]);
    if (t == 0)   atomicAdd(&g_count, sc);
}

// ---------- kernel 3a: batched exact recompute of flagged tokens ----------
// grid (16 n-blocks, 16 token stripes); block tile 16 tok x 128 n, thread 2x4
__global__ __launch_bounds__(256)
void repairA_kernel(const float* __restrict__ x, const float* __restrict__ b1,
                    const float* __restrict__ w2) {
    __shared__ float xs[16][68];
    __shared__ float ws[128][68];
    __shared__ float w2s[128 * NEXP];
    __shared__ float sew[16][NEXP];
    const int t = threadIdx.x;
    const int nb = blockIdx.x * 128;
    const int nf = min(g_nflag, MAXFLAG);
    const int tg = t & 7, ng = t >> 3;     // 2 toks, 4 n per thread

    for (int i = t; i < 128 * NEXP; i += 256) w2s[i] = w2[(size_t)nb * NEXP + i];

    for (int tokbase = blockIdx.y * 16; tokbase < nf; tokbase += 16 * gridDim.y) {
        if (t < 128) sew[t >> 3][t & 7] = 0.f;
        float acc[2][4] = {{0.f, 0.f, 0.f, 0.f}, {0.f, 0.f, 0.f, 0.f}};

        for (int kc = 0; kc < 16; ++kc) {
            __syncthreads();
            {   // xs: 16 tok x 64 k
                int row = t >> 4, col = (t & 15) * 4;
                int ti = tokbase + row;
                float4 v = make_float4(0.f, 0.f, 0.f, 0.f);
                if (ti < nf)
                    v = *(const float4*)(x + (size_t)g_list[ti] * HDIM + kc * 64 + col);
                *(float4*)&xs[row][col] = v;
            }
            {   // ws: 128 n x 64 k exact fp32
                int r = t >> 1, c0 = (t & 1) * 32;
                size_t o = (size_t)(nb + r) * HDIM + kc * 64 + c0;
                const __half2* hp = (const __half2*)(g_wh + o);
                const __half2* lp = (const __half2*)(g_wl + o);
#pragma unroll
                for (int q = 0; q < 16; ++q) {
                    float2 hf = __half22float2(hp[q]);
                    float2 lf = __half22float2(lp[q]);
                    ws[r][c0 + q * 2]     = (hf.x + lf.x) * (1.0f / 1024.0f);
                    ws[r][c0 + q * 2 + 1] = (hf.y + lf.y) * (1.0f / 1024.0f);
                }
            }
            __syncthreads();
#pragma unroll 4
            for (int kq = 0; kq < 16; ++kq) {
                float4 x0 = *(float4*)&xs[tg * 2][kq * 4];
                float4 x1 = *(float4*)&xs[tg * 2 + 1][kq * 4];
#pragma unroll
                for (int j = 0; j < 4; ++j) {
                    float4 wv = *(float4*)&ws[ng * 4 + j][kq * 4];
                    acc[0][j] = fmaf(x0.x, wv.x, fmaf(x0.y, wv.y,
                                fmaf(x0.z, wv.z, fmaf(x0.w, wv.w, acc[0][j]))));
                    acc[1][j] = fmaf(x1.x, wv.x, fmaf(x1.y, wv.y,
                                fmaf(x1.z, wv.z, fmaf(x1.w, wv.w, acc[1][j]))));
                }
            }
        }
        __syncthreads();
#pragma unroll
        for (int i = 0; i < 2; ++i) {
            float part[NEXP];
#pragma unroll
            for (int e = 0; e < NEXP; ++e) part[e] = 0.f;
#pragma unroll
            for (int j = 0; j < 4; ++j) {
                int n = ng * 4 + j;
                float v = acc[i][j] + b1[nb + n];
                float g = 0.5f * v * (1.0f + erff(v * 0.7071067811865475f));
#pragma unroll
                for (int e = 0; e < NEXP; ++e)
                    part[e] = fmaf(g, w2s[n * NEXP + e], part[e]);
            }
#pragma unroll
            for (int e = 0; e < NEXP; ++e)
                atomicAdd(&sew[tg * 2 + i][e], part[e]);
        }
        __syncthreads();
        if (t < 128) {
            int ti = tokbase + (t >> 3);
            if (ti < nf)
                atomicAdd(&g_ewfix[ti * NEXP + (t & 7)], sew[t >> 3][t & 7]);
        }
        __syncthreads();
    }
}

// ---------- kernel 3b: flagged masks/usage + losses (single block) ----------
__global__ void repairB_kernel(float* __restrict__ masks, float* __restrict__ tail, int M) {
    __shared__ float su[NEXP];
    __shared__ int sc;
    const int t = threadIdx.x;
    if (t < NEXP) su[t] = 0.f;
    if (t == 0)   sc = 0;
    __syncthreads();
    const int nf = min(g_nflag, MAXFLAG);
    for (int it = t; it < nf; it += 256) {
        const int tok = g_list[it];
        float v[NEXP];
#pragma unroll
        for (int e = 0; e < NEXP; ++e) v[e] = g_ewfix[it * NEXP + e];
        int i1 = 0; float m1 = v[0];
#pragma unroll
        for (int e = 1; e < NEXP; ++e) if (v[e] > m1) { m1 = v[e]; i1 = e; }
        int i2 = -1; float m2 = -3.4e38f;
#pragma unroll
        for (int e = 0; e < NEXP; ++e) if (e != i1 && v[e] > m2) { m2 = v[e]; i2 = e; }
        float ex = expf(m2 - m1);
        float p1 = 1.f / (1.f + ex), p2 = ex / (1.f + ex);
        float o[NEXP];
#pragma unroll
        for (int e = 0; e < NEXP; ++e) o[e] = (e == i1) ? p1 : ((e == i2) ? p2 : 0.f);
        *(float4*)(masks + (size_t)tok * NEXP)     = make_float4(o[0], o[1], o[2], o[3]);
        *(float4*)(masks + (size_t)tok * NEXP + 4) = make_float4(o[4], o[5], o[6], o[7]);
        atomicAdd(&su[i1], p1);
        atomicAdd(&su[i2], p2);
        atomicAdd(&sc, (p1 > 0.f) + (p2 > 0.f));
    }
    __syncthreads();
    if (t == 0) {
        float u[NEXP], s = 0.f;
#pragma unroll
        for (int e = 0; e < NEXP; ++e) { u[e] = g_usage[e] + su[e]; s += u[e]; }
        float lb = 0.f;
#pragma unroll
        for (int e = 0; e < NEXP; ++e) {
            float un = u[e] / s;
            tail[1 + e] = un;
            float d = un - 0.125f;
            lb += d * d;
        }
        lb *= (1.f / 8.f);
        tail[0] = lb + 0.1f * (((float)(g_count + sc) / (float)M) * 0.5f);
    }
}

// ---------- launch ----------
extern "C" void kernel_launch(void* const* d_in, const int* in_sizes, int n_in,
                              void* d_out, int out_size) {
    const float* x  = (const float*)d_in[0];
    const float* w1 = (const float*)d_in[1];
    const float* b1 = (const float*)d_in[2];
    const float* w2 = (const float*)d_in[3];
    const float* b2 = (const float*)d_in[4];
    float* out   = (float*)d_out;
    const int M  = in_sizes[0] / HDIM;
    float* ew    = out;
    float* masks = out + (size_t)M * NEXP;
    float* tail  = out + (size_t)2 * M * NEXP;

    cudaFuncSetAttribute(gemm_kernel, cudaFuncAttributeMaxDynamicSharedMemorySize, SMEM_DYN);

    pre_kernel<<<2048 + (M * NEXP + 255) / 256, 256>>>(w1, ew, b2);
    gemm_kernel<<<dim3(NDIM / BN, M / BM), 256, SMEM_DYN>>>(x, b1, w2, ew);
    topk_kernel<<<(M + 255) / 256, 256>>>(ew, masks, b2, M);
    repairA_kernel<<<dim3(16, 16), 256>>>(x, b1, w2);
    repairB_kernel<<<1, 256>>>(masks, tail, M);
}